// round 1
// baseline (speedup 1.0000x reference)
#include <cuda_runtime.h>
#include <math.h>

// Problem constants
#define B_      256
#define NIN_    6912
#define NCHUNK  16
#define NBLK    (NIN_ / NCHUNK)   // 432 blocks, each covers all 256 b x 16 n
#define THREADS 256

// Scratch: s1 (pass1 sums) and s2 (pass2 weighted sums), each [B][2][16]
__device__ float g_s1[B_ * 32];
__device__ float g_s2[B_ * 32];

__global__ void zero_kernel() {
    int i = blockIdx.x * blockDim.x + threadIdx.x;
    if (i < B_ * 32) { g_s1[i] = 0.0f; g_s2[i] = 0.0f; }
}

__device__ __forceinline__ void squash16(const float* s, float* v) {
    float n2 = 0.0f;
#pragma unroll
    for (int e = 0; e < 16; ++e) n2 = fmaf(s[e], s[e], n2);
    float f = n2 / ((1.0f + n2) * sqrtf(n2 + 1e-9f));
#pragma unroll
    for (int e = 0; e < 16; ++e) v[e] = s[e] * f;
}

// Cooperative load of W chunk for n in [n0, n0+NCHUNK) into smem.
// W global layout: [2][NIN][16][8] floats = per (j,n): 32 float4 (k = e*2 + dhalf).
// Smem row index = j*32 + k, column = n_local. Stored as Ws[n_local][j*32+k].
__device__ __forceinline__ void load_W_chunk(float4 (*Ws)[64], const float4* __restrict__ W,
                                             int n0, int tid) {
#pragma unroll
    for (int it = 0; it < (2 * NCHUNK * 32) / THREADS; ++it) {
        int flat = it * THREADS + tid;          // 0..1023
        int j  = flat >> 9;                     // 0..1
        int nl = (flat >> 5) & (NCHUNK - 1);    // 0..15
        int k  = flat & 31;                     // 0..31
        Ws[nl][j * 32 + k] = W[((size_t)(j * NIN_ + n0 + nl)) * 32 + k];
    }
}

// ---------------- Pass 1: s1[b,j,e] = sum_n sum_d W[j,n,e,d] * x[b,n,d] ----------------
__global__ __launch_bounds__(THREADS) void pass1_kernel(const float4* __restrict__ X,
                                                        const float4* __restrict__ W) {
    __shared__ float4 Ws[NCHUNK][64];
    const int tid = threadIdx.x;
    const int n0  = blockIdx.x * NCHUNK;

    load_W_chunk(Ws, W, n0, tid);
    __syncthreads();

    const int b = tid;   // each thread owns one batch element; warp = 32 consecutive b
    float acc[32];
#pragma unroll
    for (int k = 0; k < 32; ++k) acc[k] = 0.0f;

    const int xbase = (b * NIN_ + n0) * 2;   // float4 units
    float4 xa = X[xbase];
    float4 xb = X[xbase + 1];

#pragma unroll 1
    for (int n = 0; n < NCHUNK; ++n) {
        // prefetch next x
        int np = (n + 1 < NCHUNK) ? (n + 1) : n;
        float4 nxa = X[xbase + np * 2];
        float4 nxb = X[xbase + np * 2 + 1];
#pragma unroll
        for (int k = 0; k < 32; ++k) {       // k = j*16 + e
            float4 wa = Ws[n][2 * k];        // broadcast across warp
            float4 wb = Ws[n][2 * k + 1];
            float t = acc[k];
            t = fmaf(wa.x, xa.x, t);
            t = fmaf(wa.y, xa.y, t);
            t = fmaf(wa.z, xa.z, t);
            t = fmaf(wa.w, xa.w, t);
            t = fmaf(wb.x, xb.x, t);
            t = fmaf(wb.y, xb.y, t);
            t = fmaf(wb.z, xb.z, t);
            t = fmaf(wb.w, xb.w, t);
            acc[k] = t;
        }
        xa = nxa; xb = nxb;
    }

    float* dst = g_s1 + b * 32;
#pragma unroll
    for (int k = 0; k < 32; ++k) atomicAdd(dst + k, acc[k]);
}

// ---------------- Pass 2: routed weighted sum ----------------
// Per (b,n): u[j,e] = W.x ; t_j = v1[b,j].u_j ; c = softmax_j(t) ; s2 += c_j * u_j
__global__ __launch_bounds__(THREADS) void pass2_kernel(const float4* __restrict__ X,
                                                        const float4* __restrict__ W) {
    __shared__ float4 Ws[NCHUNK][64];
    const int tid = threadIdx.x;
    const int n0  = blockIdx.x * NCHUNK;

    load_W_chunk(Ws, W, n0, tid);
    __syncthreads();

    const int b = tid;

    // v1 = squash(0.5 * s1[b])  (computed redundantly per block — trivial cost)
    float v1[32];
    {
        float s[32];
#pragma unroll
        for (int k = 0; k < 32; ++k) s[k] = 0.5f * g_s1[b * 32 + k];
        squash16(s, v1);
        squash16(s + 16, v1 + 16);
    }

    float acc[32];
#pragma unroll
    for (int k = 0; k < 32; ++k) acc[k] = 0.0f;

    const int xbase = (b * NIN_ + n0) * 2;
    float4 xa = X[xbase];
    float4 xb = X[xbase + 1];

#pragma unroll 1
    for (int n = 0; n < NCHUNK; ++n) {
        int np = (n + 1 < NCHUNK) ? (n + 1) : n;
        float4 nxa = X[xbase + np * 2];
        float4 nxb = X[xbase + np * 2 + 1];

        float u[32];
#pragma unroll
        for (int k = 0; k < 32; ++k) {
            float4 wa = Ws[n][2 * k];
            float4 wb = Ws[n][2 * k + 1];
            float t;
            t = wa.x * xa.x;
            t = fmaf(wa.y, xa.y, t);
            t = fmaf(wa.z, xa.z, t);
            t = fmaf(wa.w, xa.w, t);
            t = fmaf(wb.x, xb.x, t);
            t = fmaf(wb.y, xb.y, t);
            t = fmaf(wb.z, xb.z, t);
            t = fmaf(wb.w, xb.w, t);
            u[k] = t;
        }

        float t0 = 0.0f, t1 = 0.0f;
#pragma unroll
        for (int e = 0; e < 16; ++e) {
            t0 = fmaf(v1[e],      u[e],      t0);
            t1 = fmaf(v1[16 + e], u[16 + e], t1);
        }
        // softmax over j = {0,1}
        float c0 = __fdividef(1.0f, 1.0f + __expf(t1 - t0));
        float c1 = 1.0f - c0;
#pragma unroll
        for (int e = 0; e < 16; ++e) {
            acc[e]      = fmaf(c0, u[e],      acc[e]);
            acc[16 + e] = fmaf(c1, u[16 + e], acc[16 + e]);
        }

        xa = nxa; xb = nxb;
    }

    float* dst = g_s2 + b * 32;
#pragma unroll
    for (int k = 0; k < 32; ++k) atomicAdd(dst + k, acc[k]);
}

// ---------------- Output: v = squash(s2) ----------------
__global__ void squash_out_kernel(float* __restrict__ out) {
    int t = blockIdx.x * blockDim.x + threadIdx.x;   // t = b*2 + j, 512 items
    if (t < B_ * 2) {
        float s[16], v[16];
#pragma unroll
        for (int e = 0; e < 16; ++e) s[e] = g_s2[t * 16 + e];
        squash16(s, v);
#pragma unroll
        for (int e = 0; e < 16; ++e) out[t * 16 + e] = v[e];
    }
}

extern "C" void kernel_launch(void* const* d_in, const int* in_sizes, int n_in,
                              void* d_out, int out_size) {
    const float4* X = (const float4*)d_in[0];   // x: [256, 6912, 8] f32
    const float4* W = (const float4*)d_in[1];   // W: [2, 6912, 16, 8] f32
    float* out = (float*)d_out;                 // v: [256, 2, 16] f32

    zero_kernel<<<32, 256>>>();
    pass1_kernel<<<NBLK, THREADS>>>(X, W);
    pass2_kernel<<<NBLK, THREADS>>>(X, W);
    squash_out_kernel<<<2, 256>>>(out);
}

// round 2
// speedup vs baseline: 1.4759x; 1.4759x over previous
#include <cuda_runtime.h>
#include <math.h>

// Problem constants
#define B_      256
#define NIN_    6912
#define NCHUNK  8
#define NBLK    (NIN_ / NCHUNK)   // 864 blocks
#define SLOTS   8                 // atomic slot-split factor
#define THREADS 256

// Scratch, transposed layout [slot][k][b] (k = j*16+e), so warp-lane atomics coalesce.
__device__ float g_s1[SLOTS * B_ * 32];
__device__ float g_s2[SLOTS * B_ * 32];
__device__ float g_v1[B_ * 32];          // v1 transposed: [k][b]

__global__ void zero_kernel() {
    int i = blockIdx.x * blockDim.x + threadIdx.x;
    if (i < SLOTS * B_ * 32) { g_s1[i] = 0.0f; g_s2[i] = 0.0f; }
}

__device__ __forceinline__ void squash16(const float* s, float* v) {
    float n2 = 0.0f;
#pragma unroll
    for (int e = 0; e < 16; ++e) n2 = fmaf(s[e], s[e], n2);
    float f = n2 / ((1.0f + n2) * sqrtf(n2 + 1e-9f));
#pragma unroll
    for (int e = 0; e < 16; ++e) v[e] = s[e] * f;
}

// Cooperative load of W chunk for n in [n0, n0+NCHUNK) into smem.
// W layout: [2][NIN][16][8] floats -> per (j,n): 32 float4 (k' = e*2 + half).
__device__ __forceinline__ void load_W_chunk(float4 (*Ws)[64], const float4* __restrict__ W,
                                             int n0, int tid) {
#pragma unroll
    for (int it = 0; it < (2 * NCHUNK * 32) / THREADS; ++it) {
        int flat = it * THREADS + tid;          // 0..511
        int j  = flat >> 8;                     // 0..1
        int nl = (flat >> 5) & (NCHUNK - 1);    // 0..7
        int k  = flat & 31;                     // 0..31
        Ws[nl][j * 32 + k] = W[((size_t)(j * NIN_ + n0 + nl)) * 32 + k];
    }
}

// ---------------- Pass 1: s1[b,j,e] = sum_n sum_d W[j,n,e,d] * x[b,n,d] ----------------
__global__ __launch_bounds__(THREADS, 2) void pass1_kernel(const float4* __restrict__ X,
                                                           const float4* __restrict__ W) {
    __shared__ float4 Ws[NCHUNK][64];
    const int tid = threadIdx.x;
    const int n0  = blockIdx.x * NCHUNK;

    load_W_chunk(Ws, W, n0, tid);
    __syncthreads();

    const int b = tid;   // thread owns one batch element; warp = 32 consecutive b
    float acc[32];
#pragma unroll
    for (int k = 0; k < 32; ++k) acc[k] = 0.0f;

    const int xbase = (b * NIN_ + n0) * 2;   // float4 units

#pragma unroll
    for (int n = 0; n < NCHUNK; ++n) {
        float4 xa = X[xbase + n * 2];
        float4 xb = X[xbase + n * 2 + 1];
#pragma unroll
        for (int k = 0; k < 32; ++k) {       // k = j*16 + e
            float4 wa = Ws[n][2 * k];        // warp-broadcast
            float4 wb = Ws[n][2 * k + 1];
            float t = acc[k];
            t = fmaf(wa.x, xa.x, t);
            t = fmaf(wa.y, xa.y, t);
            t = fmaf(wa.z, xa.z, t);
            t = fmaf(wa.w, xa.w, t);
            t = fmaf(wb.x, xb.x, t);
            t = fmaf(wb.y, xb.y, t);
            t = fmaf(wb.z, xb.z, t);
            t = fmaf(wb.w, xb.w, t);
            acc[k] = t;
        }
    }

    float* dst = g_s1 + (blockIdx.x & (SLOTS - 1)) * (B_ * 32);
#pragma unroll
    for (int k = 0; k < 32; ++k) atomicAdd(dst + k * B_ + b, acc[k]);   // coalesced REDG
}

// ---------------- v1 = squash(0.5 * sum_slots s1) ----------------
__global__ void v1_kernel() {
    const int b = threadIdx.x;
    float s[32];
#pragma unroll
    for (int k = 0; k < 32; ++k) s[k] = 0.0f;
#pragma unroll
    for (int sl = 0; sl < SLOTS; ++sl)
#pragma unroll
        for (int k = 0; k < 32; ++k)
            s[k] += g_s1[sl * (B_ * 32) + k * B_ + b];
#pragma unroll
    for (int k = 0; k < 32; ++k) s[k] *= 0.5f;
    float v[32];
    squash16(s, v);
    squash16(s + 16, v + 16);
#pragma unroll
    for (int k = 0; k < 32; ++k) g_v1[k * B_ + b] = v[k];
}

// ---------------- Pass 2: routed weighted sum ----------------
__global__ __launch_bounds__(THREADS, 2) void pass2_kernel(const float4* __restrict__ X,
                                                           const float4* __restrict__ W) {
    __shared__ float4 Ws[NCHUNK][64];
    const int tid = threadIdx.x;
    const int n0  = blockIdx.x * NCHUNK;

    load_W_chunk(Ws, W, n0, tid);
    __syncthreads();

    const int b = tid;

    float v1[32];
#pragma unroll
    for (int k = 0; k < 32; ++k) v1[k] = g_v1[k * B_ + b];   // coalesced

    float acc[32];
#pragma unroll
    for (int k = 0; k < 32; ++k) acc[k] = 0.0f;

    const int xbase = (b * NIN_ + n0) * 2;

#pragma unroll
    for (int n = 0; n < NCHUNK; ++n) {
        float4 xa = X[xbase + n * 2];
        float4 xb = X[xbase + n * 2 + 1];

        float u[32];
#pragma unroll
        for (int k = 0; k < 32; ++k) {
            float4 wa = Ws[n][2 * k];
            float4 wb = Ws[n][2 * k + 1];
            float t;
            t = wa.x * xa.x;
            t = fmaf(wa.y, xa.y, t);
            t = fmaf(wa.z, xa.z, t);
            t = fmaf(wa.w, xa.w, t);
            t = fmaf(wb.x, xb.x, t);
            t = fmaf(wb.y, xb.y, t);
            t = fmaf(wb.z, xb.z, t);
            t = fmaf(wb.w, xb.w, t);
            u[k] = t;
        }

        float t0 = 0.0f, t1 = 0.0f;
#pragma unroll
        for (int e = 0; e < 16; ++e) {
            t0 = fmaf(v1[e],      u[e],      t0);
            t1 = fmaf(v1[16 + e], u[16 + e], t1);
        }
        float c0 = __fdividef(1.0f, 1.0f + __expf(t1 - t0));
        float c1 = 1.0f - c0;
#pragma unroll
        for (int e = 0; e < 16; ++e) {
            acc[e]      = fmaf(c0, u[e],      acc[e]);
            acc[16 + e] = fmaf(c1, u[16 + e], acc[16 + e]);
        }
    }

    float* dst = g_s2 + (blockIdx.x & (SLOTS - 1)) * (B_ * 32);
#pragma unroll
    for (int k = 0; k < 32; ++k) atomicAdd(dst + k * B_ + b, acc[k]);
}

// ---------------- Output: v = squash(sum_slots s2) ----------------
__global__ void squash_out_kernel(float* __restrict__ out) {
    int t = blockIdx.x * blockDim.x + threadIdx.x;   // t = b*2 + j, 512 items
    if (t < B_ * 2) {
        int b = t >> 1, j = t & 1;
        float s[16];
#pragma unroll
        for (int e = 0; e < 16; ++e) s[e] = 0.0f;
#pragma unroll
        for (int sl = 0; sl < SLOTS; ++sl)
#pragma unroll
            for (int e = 0; e < 16; ++e)
                s[e] += g_s2[sl * (B_ * 32) + (j * 16 + e) * B_ + b];
        float v[16];
        squash16(s, v);
#pragma unroll
        for (int e = 0; e < 16; ++e) out[t * 16 + e] = v[e];
    }
}

extern "C" void kernel_launch(void* const* d_in, const int* in_sizes, int n_in,
                              void* d_out, int out_size) {
    const float4* X = (const float4*)d_in[0];   // x: [256, 6912, 8] f32
    const float4* W = (const float4*)d_in[1];   // W: [2, 6912, 16, 8] f32
    float* out = (float*)d_out;                 // v: [256, 2, 16] f32

    zero_kernel<<<(SLOTS * B_ * 32 + 255) / 256, 256>>>();
    pass1_kernel<<<NBLK, THREADS>>>(X, W);
    v1_kernel<<<1, B_>>>();
    pass2_kernel<<<NBLK, THREADS>>>(X, W);
    squash_out_kernel<<<2, 256>>>(out);
}

// round 3
// speedup vs baseline: 1.6655x; 1.1284x over previous
#include <cuda_runtime.h>
#include <math.h>

#define B_      256
#define NIN_    6912
#define NCHUNK  4
#define NBLK    (NIN_ / NCHUNK)   // 1728 blocks
#define SLOTS   8
#define THREADS 256

// f32x2 packed FMA (sm_100+): d = a*b + c elementwise on packed float pairs
#define FFMA2(d, a, b, c) \
    asm("fma.rn.f32x2 %0, %1, %2, %3;" : "=l"(d) : "l"(a), "l"(b), "l"(c))
#define PACK2(d, lo, hi) \
    asm("mov.b64 %0, {%1, %2};" : "=l"(d) : "f"(lo), "f"(hi))
#define UNPACK2(lo, hi, v) \
    asm("mov.b64 {%0, %1}, %2;" : "=f"(lo), "=f"(hi) : "l"(v))

// Scratch, transposed [slot][k][b] so warp atomics coalesce.
__device__ float g_s1[SLOTS * B_ * 32];
__device__ float g_s2[SLOTS * B_ * 32];
__device__ float g_v1[B_ * 32];

__global__ void zero_kernel() {
    int i = blockIdx.x * blockDim.x + threadIdx.x;
    if (i < SLOTS * B_ * 32) { g_s1[i] = 0.0f; g_s2[i] = 0.0f; }
}

__device__ __forceinline__ void squash16(const float* s, float* v) {
    float n2 = 0.0f;
#pragma unroll
    for (int e = 0; e < 16; ++e) n2 = fmaf(s[e], s[e], n2);
    float f = n2 / ((1.0f + n2) * sqrtf(n2 + 1e-9f));
#pragma unroll
    for (int e = 0; e < 16; ++e) v[e] = s[e] * f;
}

// W chunk -> smem: Ws[nl][j*32 + e*2 + h] (float4). 256 float4 per chunk = 1/thread.
__device__ __forceinline__ void load_W_chunk(float4 (*Ws)[64], const float4* __restrict__ W,
                                             int n0, int tid) {
    int j  = tid >> 7;                  // 0..1
    int nl = (tid >> 5) & (NCHUNK - 1); // 0..3
    int k  = tid & 31;                  // 0..31
    Ws[nl][j * 32 + k] = W[((size_t)(j * NIN_ + n0 + nl)) * 32 + k];
}

// x chunk -> smem, transposed + packed: xs[nl][dp][b] = (x[b][n0+nl][2dp], x[b][n0+nl][2dp+1])
// Pad b-dim by 1 (stride 257) to avoid STS bank conflicts on transposed writes.
__device__ __forceinline__ void load_x_chunk(unsigned long long (*xs)[4][B_ + 1],
                                             const float4* __restrict__ X,
                                             int n0, int tid) {
#pragma unroll
    for (int it = 0; it < (B_ * NCHUNK * 2) / THREADS; ++it) {   // 8 iters
        int f  = it * THREADS + tid;       // 0..2047
        int b  = f >> 3;                   // 0..255 (8 float4 per b per chunk)
        int q  = f & 7;
        int nl = q >> 1;                   // 0..3
        int dh = q & 1;                    // 0..1
        float4 v = X[((size_t)b * NIN_ + n0 + nl) * 2 + dh];
        unsigned long long p0, p1;
        PACK2(p0, v.x, v.y);
        PACK2(p1, v.z, v.w);
        xs[nl][dh * 2][b]     = p0;
        xs[nl][dh * 2 + 1][b] = p1;
    }
}

// ---------------- Pass 1 ----------------
__global__ __launch_bounds__(THREADS, 2) void pass1_kernel(const float4* __restrict__ X,
                                                           const float4* __restrict__ W) {
    __shared__ float4 Ws[NCHUNK][64];
    __shared__ unsigned long long xs[NCHUNK][4][B_ + 1];
    const int tid = threadIdx.x;
    const int n0  = blockIdx.x * NCHUNK;

    load_W_chunk(Ws, W, n0, tid);
    load_x_chunk(xs, X, n0, tid);
    __syncthreads();

    const int b = tid;
    unsigned long long acc2[32];
    unsigned long long zero;
    PACK2(zero, 0.0f, 0.0f);
#pragma unroll
    for (int k = 0; k < 32; ++k) acc2[k] = zero;

#pragma unroll
    for (int n = 0; n < NCHUNK; ++n) {
        unsigned long long x0 = xs[n][0][b];
        unsigned long long x1 = xs[n][1][b];
        unsigned long long x2 = xs[n][2][b];
        unsigned long long x3 = xs[n][3][b];
#pragma unroll
        for (int k = 0; k < 32; ++k) {
            const ulonglong2 wA = *reinterpret_cast<const ulonglong2*>(&Ws[n][2 * k]);
            const ulonglong2 wB = *reinterpret_cast<const ulonglong2*>(&Ws[n][2 * k + 1]);
            unsigned long long a = acc2[k];
            FFMA2(a, wA.x, x0, a);
            FFMA2(a, wA.y, x1, a);
            FFMA2(a, wB.x, x2, a);
            FFMA2(a, wB.y, x3, a);
            acc2[k] = a;
        }
    }

    float* dst = g_s1 + (blockIdx.x & (SLOTS - 1)) * (B_ * 32);
#pragma unroll
    for (int k = 0; k < 32; ++k) {
        float lo, hi;
        UNPACK2(lo, hi, acc2[k]);
        atomicAdd(dst + k * B_ + b, lo + hi);
    }
}

// ---------------- v1 = squash(0.5 * sum_slots s1) ----------------
__global__ void v1_kernel() {
    const int b = threadIdx.x;
    float s[32];
#pragma unroll
    for (int k = 0; k < 32; ++k) s[k] = 0.0f;
#pragma unroll
    for (int sl = 0; sl < SLOTS; ++sl)
#pragma unroll
        for (int k = 0; k < 32; ++k)
            s[k] += g_s1[sl * (B_ * 32) + k * B_ + b];
#pragma unroll
    for (int k = 0; k < 32; ++k) s[k] *= 0.5f;
    float v[32];
    squash16(s, v);
    squash16(s + 16, v + 16);
#pragma unroll
    for (int k = 0; k < 32; ++k) g_v1[k * B_ + b] = v[k];
}

// ---------------- Pass 2 ----------------
__global__ __launch_bounds__(THREADS, 2) void pass2_kernel(const float4* __restrict__ X,
                                                           const float4* __restrict__ W) {
    __shared__ float4 Ws[NCHUNK][64];
    __shared__ unsigned long long xs[NCHUNK][4][B_ + 1];
    const int tid = threadIdx.x;
    const int n0  = blockIdx.x * NCHUNK;

    load_W_chunk(Ws, W, n0, tid);
    load_x_chunk(xs, X, n0, tid);
    __syncthreads();

    const int b = tid;

    float v1[32];
#pragma unroll
    for (int k = 0; k < 32; ++k) v1[k] = g_v1[k * B_ + b];

    float acc[32];
#pragma unroll
    for (int k = 0; k < 32; ++k) acc[k] = 0.0f;

#pragma unroll
    for (int n = 0; n < NCHUNK; ++n) {
        unsigned long long x0 = xs[n][0][b];
        unsigned long long x1 = xs[n][1][b];
        unsigned long long x2 = xs[n][2][b];
        unsigned long long x3 = xs[n][3][b];

        float u[32];
#pragma unroll
        for (int k = 0; k < 32; ++k) {
            const ulonglong2 wA = *reinterpret_cast<const ulonglong2*>(&Ws[n][2 * k]);
            const ulonglong2 wB = *reinterpret_cast<const ulonglong2*>(&Ws[n][2 * k + 1]);
            unsigned long long t;
            asm("mul.rn.f32x2 %0, %1, %2;" : "=l"(t) : "l"(wA.x), "l"(x0));
            FFMA2(t, wA.y, x1, t);
            FFMA2(t, wB.x, x2, t);
            FFMA2(t, wB.y, x3, t);
            float lo, hi;
            UNPACK2(lo, hi, t);
            u[k] = lo + hi;
        }

        float t0 = 0.0f, t1 = 0.0f;
#pragma unroll
        for (int e = 0; e < 16; ++e) {
            t0 = fmaf(v1[e],      u[e],      t0);
            t1 = fmaf(v1[16 + e], u[16 + e], t1);
        }
        float c0 = __fdividef(1.0f, 1.0f + __expf(t1 - t0));
        float c1 = 1.0f - c0;
#pragma unroll
        for (int e = 0; e < 16; ++e) {
            acc[e]      = fmaf(c0, u[e],      acc[e]);
            acc[16 + e] = fmaf(c1, u[16 + e], acc[16 + e]);
        }
    }

    float* dst = g_s2 + (blockIdx.x & (SLOTS - 1)) * (B_ * 32);
#pragma unroll
    for (int k = 0; k < 32; ++k) atomicAdd(dst + k * B_ + b, acc[k]);
}

// ---------------- Output ----------------
__global__ void squash_out_kernel(float* __restrict__ out) {
    int t = blockIdx.x * blockDim.x + threadIdx.x;   // t = b*2 + j
    if (t < B_ * 2) {
        int b = t >> 1, j = t & 1;
        float s[16];
#pragma unroll
        for (int e = 0; e < 16; ++e) s[e] = 0.0f;
#pragma unroll
        for (int sl = 0; sl < SLOTS; ++sl)
#pragma unroll
            for (int e = 0; e < 16; ++e)
                s[e] += g_s2[sl * (B_ * 32) + (j * 16 + e) * B_ + b];
        float v[16];
        squash16(s, v);
#pragma unroll
        for (int e = 0; e < 16; ++e) out[t * 16 + e] = v[e];
    }
}

extern "C" void kernel_launch(void* const* d_in, const int* in_sizes, int n_in,
                              void* d_out, int out_size) {
    const float4* X = (const float4*)d_in[0];   // x: [256, 6912, 8] f32
    const float4* W = (const float4*)d_in[1];   // W: [2, 6912, 16, 8] f32
    float* out = (float*)d_out;                 // v: [256, 2, 16] f32

    zero_kernel<<<(SLOTS * B_ * 32 + 255) / 256, 256>>>();
    pass1_kernel<<<NBLK, THREADS>>>(X, W);
    v1_kernel<<<1, B_>>>();
    pass2_kernel<<<NBLK, THREADS>>>(X, W);
    squash_out_kernel<<<2, 256>>>(out);
}